// round 6
// baseline (speedup 1.0000x reference)
#include <cuda_runtime.h>
#include <math.h>

#define T_ 100
#define B_ 64
#define I_ 256
#define H_ 512
#define G4_ (4*H_)   // 2048
#define H3_ (3*H_)   // 1536
#define BH_ (B_*H_)  // 32768
#define NBLK_ 128    // persistent blocks (<=148 SMs, all wave-1 resident)

typedef unsigned long long u64;

// ---------------- scratch (device globals) -----------------------------------
__device__ float g_xproj[(size_t)T_*B_*G4_];   // [T*B][4H] input-path gates + biases
__device__ float g_hseq[(size_t)(T_+1)*BH_];   // hseq[t] = h_{t-1} (for ev_hh GEMM)
__device__ u64   g_hT[2][(size_t)H_*B_/2];     // double-buffered transposed h [512][64]
__device__ float g_f[(size_t)T_*BH_];          // forget gates
__device__ float g_d[(size_t)T_*B_*H3_];       // d_i|d_f|d_g; suffix-scaled in place
__device__ unsigned g_arrive;                  // grid-barrier monotonic arrival counter

// ---------------- helpers -----------------------------------------------------
__device__ __forceinline__ void unpack2(u64 v, float& x, float& y) {
    asm("mov.b64 {%0,%1}, %2;" : "=f"(x), "=f"(y) : "l"(v));
}
__device__ __forceinline__ u64 ldcg64(const u64* p) {
    u64 v; asm volatile("ld.global.cg.b64 %0, [%1];" : "=l"(v) : "l"(p)); return v;
}
__device__ __forceinline__ unsigned ldacq32(const unsigned* p) {
    unsigned v; asm volatile("ld.acquire.gpu.global.u32 %0, [%1];" : "=r"(v) : "l"(p)); return v;
}

// ---------------- init --------------------------------------------------------
__global__ void k_init(const float* __restrict__ h0) {
    int i = blockIdx.x*256 + threadIdx.x;
    if (i < BH_) {
        g_hseq[i] = h0[i];
        int b = i >> 9, k = i & 511;
        ((float*)g_hT[0])[k*B_ + b] = h0[i];
    }
    if (i == 0) g_arrive = 0u;
}

// ---------------- K1: xproj = X @ Wih^T + b_ih + b_hh -------------------------
__global__ __launch_bounds__(256, 2) void k1_xproj(
    const float* __restrict__ X, const float* __restrict__ W,
    const float* __restrict__ bih, const float* __restrict__ bhh)
{
    __shared__ float As[8][132];
    __shared__ float Ws[8][132];
    int m0 = blockIdx.y * 128;
    int n0 = blockIdx.x * 128;
    int tid = threadIdx.x;
    int lc = tid % 8;
    int lr = tid / 8;
    int ty = tid / 16, tx = tid % 16;

    float acc[8][8];
    #pragma unroll
    for (int i=0;i<8;i++)
        #pragma unroll
        for (int j=0;j<8;j++) acc[i][j]=0.f;

    for (int k0 = 0; k0 < I_; k0 += 8) {
        #pragma unroll
        for (int p = 0; p < 4; p++) {
            int r = lr + p*32;
            As[lc][r] = X[(size_t)(m0 + r)*I_ + k0 + lc];
            Ws[lc][r] = W[(size_t)(n0 + r)*I_ + k0 + lc];
        }
        __syncthreads();
        #pragma unroll
        for (int kk = 0; kk < 8; kk++) {
            float4 a0 = *(const float4*)&As[kk][ty*4];
            float4 a1 = *(const float4*)&As[kk][64 + ty*4];
            float4 b0 = *(const float4*)&Ws[kk][tx*4];
            float4 b1 = *(const float4*)&Ws[kk][64 + tx*4];
            float a[8] = {a0.x,a0.y,a0.z,a0.w,a1.x,a1.y,a1.z,a1.w};
            float bb[8]= {b0.x,b0.y,b0.z,b0.w,b1.x,b1.y,b1.z,b1.w};
            #pragma unroll
            for (int i=0;i<8;i++)
                #pragma unroll
                for (int j=0;j<8;j++) acc[i][j] += a[i]*bb[j];
        }
        __syncthreads();
    }
    float bias[8];
    #pragma unroll
    for (int j=0;j<8;j++) {
        int n = n0 + ((j<4)? tx*4 + j : 64 + tx*4 + (j-4));
        bias[j] = bih[n] + bhh[n];
    }
    #pragma unroll
    for (int i=0;i<8;i++) {
        int m = m0 + ((i<4)? ty*4+i : 64+ty*4+(i-4));
        float* row = g_xproj + (size_t)m*G4_ + n0;
        float4 v0 = make_float4(acc[i][0]+bias[0], acc[i][1]+bias[1],
                                acc[i][2]+bias[2], acc[i][3]+bias[3]);
        float4 v1 = make_float4(acc[i][4]+bias[4], acc[i][5]+bias[5],
                                acc[i][6]+bias[6], acc[i][7]+bias[7]);
        *(float4*)&row[tx*4]      = v0;
        *(float4*)&row[64+tx*4]   = v1;
    }
}

// ---------------- persistent recurrence kernel --------------------------------
// 128 blocks x 256 thr. Block owns h-cols hg = bid*4..bid*4+3 (16 gate cols).
// Static smem: Wd [512][16] floats (32KB) + exch 2048 floats (8KB) = 40KB.
__global__ __launch_bounds__(256, 1) void k_rec(
    const float* __restrict__ Whh, const float* __restrict__ c0,
    float* __restrict__ out_h, float* __restrict__ out_cx)
{
    __shared__ float Wd[512*16];   // Wd[k*16 + q*4 + hl] = Whh[q*H + bid*4+hl][k]
    __shared__ float exch[2048];   // [kh][q][b][hl]

    int bid = blockIdx.x;
    int tid = threadIdx.x;

    {
        int l  = tid & 15;
        int k0 = tid >> 4;           // 0..15
        int n  = (l>>2)*H_ + bid*4 + (l&3);
        for (int k = k0; k < H_; k += 16)
            Wd[k*16 + l] = Whh[(size_t)n*H_ + k];
    }

    // pointwise cell ownership
    int pb  = tid >> 2;
    int phl = tid & 3;
    int hg  = bid*4 + phl;
    float c = c0[pb*H_ + hg];

    // GEMM warp mapping
    int w      = tid >> 5;
    int lane   = tid & 31;
    int bq     = w & 3;
    int khalf  = w >> 2;
    int bp     = lane >> 2;          // 0..7
    int q      = lane & 3;           // gate
    int b0     = bq*16 + bp*2;
    int hidx   = b0 >> 1;            // u64 index into hT row
    int kbase  = khalf * 256;

    __syncthreads();

    for (int t = 0; t < T_; ++t) {
        // ---- GEMM over this warp's k-half (scalar FFMA) ----
        const u64* hp = g_hT[t & 1];
        float a00=0.f,a01=0.f,a02=0.f,a03=0.f;
        float a10=0.f,a11=0.f,a12=0.f,a13=0.f;
        u64 hb[8];
        #pragma unroll
        for (int j=0;j<8;j++) hb[j] = ldcg64(&hp[(size_t)(kbase+j)*32 + hidx]);
        for (int kc = 0; kc < 256; kc += 8) {
            u64 hc[8];
            #pragma unroll
            for (int j=0;j<8;j++) hc[j] = hb[j];
            if (kc + 8 < 256) {
                #pragma unroll
                for (int j=0;j<8;j++)
                    hb[j] = ldcg64(&hp[(size_t)(kbase+kc+8+j)*32 + hidx]);
            }
            #pragma unroll
            for (int j=0;j<8;j++) {
                float hx, hy; unpack2(hc[j], hx, hy);
                float4 wv = *(const float4*)&Wd[(kbase+kc+j)*16 + q*4];
                a00 += hx*wv.x; a01 += hx*wv.y; a02 += hx*wv.z; a03 += hx*wv.w;
                a10 += hy*wv.x; a11 += hy*wv.y; a12 += hy*wv.z; a13 += hy*wv.w;
            }
        }
        // ---- exchange: exch[kh][q][b][hl] ----
        {
            int base = ((khalf*4 + q)*64 + b0)*4;
            exch[base+0]=a00; exch[base+1]=a01; exch[base+2]=a02; exch[base+3]=a03;
            exch[base+4]=a10; exch[base+5]=a11; exch[base+6]=a12; exch[base+7]=a13;
        }
        __syncthreads();

        // ---- pointwise for cell (pb, hg); h writes go to write buffer ----
        {
            const float* xp = g_xproj + ((size_t)t*B_ + pb)*G4_;
            float ai = xp[hg]       + exch[((0*4+0)*64+pb)*4+phl] + exch[((1*4+0)*64+pb)*4+phl];
            float af = xp[H_+hg]    + exch[((0*4+1)*64+pb)*4+phl] + exch[((1*4+1)*64+pb)*4+phl];
            float ag = xp[2*H_+hg]  + exch[((0*4+2)*64+pb)*4+phl] + exch[((1*4+2)*64+pb)*4+phl];
            float ao = xp[3*H_+hg]  + exch[((0*4+3)*64+pb)*4+phl] + exch[((1*4+3)*64+pb)*4+phl];

            float ig = 1.f/(1.f+expf(-ai));
            float fg = 1.f/(1.f+expf(-af));
            float gg = tanhf(ag);
            float og = 1.f/(1.f+expf(-ao));
            float cprev = c;
            float cy = fg*cprev + ig*gg;
            float hy = og*tanhf(cy);
            c = cy;

            size_t oidx = (size_t)t*BH_ + pb*H_ + hg;
            out_h[oidx] = hy;
            g_hseq[(size_t)(t+1)*BH_ + pb*H_ + hg] = hy;
            ((float*)g_hT[(t+1) & 1])[hg*B_ + pb] = hy;   // write buffer
            g_f[oidx] = fg;
            float* dp = g_d + ((size_t)t*B_ + pb)*H3_;
            dp[hg]        = gg*ig*(1.f-ig);
            dp[H_+hg]     = cprev*fg*(1.f-fg);
            dp[2*H_+hg]   = ig*(1.f-gg*gg);
            if (t == T_-1) out_cx[pb*H_ + hg] = cy;
        }

        // ---- grid barrier (release: fence+arrive; acquire: spin+sync) ----
        __threadfence();
        __syncthreads();
        if (tid == 0) {
            atomicAdd(&g_arrive, 1u);
            unsigned target = (unsigned)(NBLK_ * (t+1));
            while (ldacq32(&g_arrive) < target) { }
        }
        __syncthreads();
    }
}

// ---------------- K3: suffix forget-product scan; ev_b -------------------------
__global__ void k3_suffix(float* __restrict__ out_evb)
{
    int idx = blockIdx.x*256 + threadIdx.x;   // < BH_
    int b = idx >> 9;
    int h = idx & 511;
    float p = 1.f, s0 = 0.f, s1 = 0.f, s2 = 0.f;
    for (int t = T_-1; t >= 0; --t) {
        float* dp = g_d + ((size_t)t*B_ + b)*H3_;
        float di = dp[h]*p, df = dp[H_+h]*p, dg = dp[2*H_+h]*p;
        dp[h] = di; dp[H_+h] = df; dp[2*H_+h] = dg;
        s0 += di; s1 += df; s2 += dg;
        p *= g_f[(size_t)t*BH_ + idx];
    }
    out_evb[(size_t)b*H3_ + h]        = s0;
    out_evb[(size_t)b*H3_ + H_ + h]   = s1;
    out_evb[(size_t)b*H3_ + 2*H_ + h] = s2;
}

// ---------------- K4/K5: batched ev GEMM --------------------------------------
__global__ __launch_bounds__(256, 2) void k_ev(
    const float* __restrict__ Xin, float* __restrict__ C, int Idim)
{
    __shared__ float As[8][132];
    __shared__ float Xs[8][132];
    const float* X = Xin ? Xin : (const float*)g_hseq;
    int i0 = blockIdx.x*128;
    int j0 = blockIdx.y*128;
    int b  = blockIdx.z;
    int tid = threadIdx.x;
    int ty = tid/16, tx = tid%16;
    int lk = tid >> 5;
    int lj = (tid & 31) * 4;

    float acc[8][8];
    #pragma unroll
    for (int i=0;i<8;i++)
        #pragma unroll
        for (int j=0;j<8;j++) acc[i][j]=0.f;

    for (int t0 = 0; t0 < T_; t0 += 8) {
        int t = t0 + lk;
        if (t < T_) {
            *(float4*)&As[lk][lj] = *(const float4*)&g_d[((size_t)t*B_+b)*H3_ + j0 + lj];
            *(float4*)&Xs[lk][lj] = *(const float4*)&X[((size_t)t*B_+b)*Idim + i0 + lj];
        } else {
            float4 z = make_float4(0.f,0.f,0.f,0.f);
            *(float4*)&As[lk][lj] = z;
            *(float4*)&Xs[lk][lj] = z;
        }
        __syncthreads();
        #pragma unroll
        for (int kk=0;kk<8;kk++) {
            float4 a0 = *(const float4*)&As[kk][ty*4];
            float4 a1 = *(const float4*)&As[kk][64+ty*4];
            float4 x0 = *(const float4*)&Xs[kk][tx*4];
            float4 x1 = *(const float4*)&Xs[kk][64+tx*4];
            float a[8] = {a0.x,a0.y,a0.z,a0.w,a1.x,a1.y,a1.z,a1.w};
            float x[8] = {x0.x,x0.y,x0.z,x0.w,x1.x,x1.y,x1.z,x1.w};
            #pragma unroll
            for (int i=0;i<8;i++)
                #pragma unroll
                for (int j=0;j<8;j++) acc[i][j] += a[i]*x[j];
        }
        __syncthreads();
    }
    #pragma unroll
    for (int i=0;i<8;i++) {
        int j = j0 + ((i<4)? ty*4+i : 64+ty*4+(i-4));
        float* row = C + (size_t)b*H3_*Idim + (size_t)j*Idim + i0;
        *(float4*)&row[tx*4]    = make_float4(acc[i][0],acc[i][1],acc[i][2],acc[i][3]);
        *(float4*)&row[64+tx*4] = make_float4(acc[i][4],acc[i][5],acc[i][6],acc[i][7]);
    }
}

// ---------------- launch -------------------------------------------------------
extern "C" void kernel_launch(void* const* d_in, const int* in_sizes, int n_in,
                              void* d_out, int out_size)
{
    const float* input = (const float*)d_in[0];
    const float* h0    = (const float*)d_in[1];
    const float* c0    = (const float*)d_in[2];
    const float* Wih   = (const float*)d_in[3];
    const float* Whh   = (const float*)d_in[4];
    const float* bih   = (const float*)d_in[5];
    const float* bhh   = (const float*)d_in[6];

    float* out      = (float*)d_out;
    float* out_h    = out;
    float* out_cx   = out_h  + (size_t)T_*BH_;
    float* out_evih = out_cx + BH_;
    float* out_evhh = out_evih + (size_t)B_*H3_*I_;
    float* out_evb  = out_evhh + (size_t)B_*H3_*H_;

    k_init<<<128,256>>>(h0);
    k1_xproj<<<dim3(16,50),256>>>(input, Wih, bih, bhh);
    k_rec<<<NBLK_, 256>>>(Whh, c0, out_h, out_cx);
    k3_suffix<<<128,256>>>(out_evb);
    k_ev<<<dim3(I_/128, H3_/128, B_),256>>>(input, out_evih, I_);
    k_ev<<<dim3(H_/128, H3_/128, B_),256>>>(nullptr, out_evhh, H_);
}

// round 7
// speedup vs baseline: 1.1957x; 1.1957x over previous
#include <cuda_runtime.h>
#include <math.h>

#define T_ 100
#define B_ 64
#define I_ 256
#define H_ 512
#define G4_ (4*H_)   // 2048
#define H3_ (3*H_)   // 1536
#define BH_ (B_*H_)  // 32768
#define NBLK_ 128    // persistent blocks (<=148 SMs, all wave-1 resident)

typedef unsigned long long u64;

// ---------------- scratch (device globals) -----------------------------------
__device__ float g_xproj[(size_t)T_*B_*G4_];   // [T*B][4H] input-path gates + biases
__device__ float g_hseq[(size_t)(T_+1)*BH_];   // hseq[t] = h_{t-1} (for ev_hh GEMM)
__device__ u64   g_hT[2][(size_t)H_*B_/2];     // double-buffered transposed h [512][64]
__device__ float g_f[(size_t)T_*BH_];          // forget gates
__device__ float g_d[(size_t)T_*B_*H3_];       // d_i|d_f|d_g; suffix-scaled in place
__device__ unsigned g_arrive;                  // grid-barrier monotonic arrival counter

// ---------------- helpers -----------------------------------------------------
__device__ __forceinline__ u64 pack2(float x, float y) {
    u64 r; asm("mov.b64 %0, {%1,%2};" : "=l"(r) : "f"(x), "f"(y)); return r;
}
__device__ __forceinline__ void unpack2(u64 v, float& x, float& y) {
    asm("mov.b64 {%0,%1}, %2;" : "=f"(x), "=f"(y) : "l"(v));
}
__device__ __forceinline__ u64 fma2(u64 a, u64 b, u64 c) {
    u64 d; asm("fma.rn.f32x2 %0, %1, %2, %3;" : "=l"(d) : "l"(a), "l"(b), "l"(c)); return d;
}
__device__ __forceinline__ u64 ldcg64(const u64* p) {
    u64 v; asm volatile("ld.global.cg.b64 %0, [%1];" : "=l"(v) : "l"(p)); return v;
}
__device__ __forceinline__ unsigned ldacq32(const unsigned* p) {
    unsigned v; asm volatile("ld.acquire.gpu.global.u32 %0, [%1];" : "=r"(v) : "l"(p)); return v;
}

// ---------------- init --------------------------------------------------------
__global__ void k_init(const float* __restrict__ h0) {
    int i = blockIdx.x*256 + threadIdx.x;
    if (i < BH_) {
        g_hseq[i] = h0[i];
        int b = i >> 9, k = i & 511;
        ((float*)g_hT[0])[k*B_ + b] = h0[i];
    }
    if (i == 0) g_arrive = 0u;
}

// ---------------- K1: xproj = X @ Wih^T + b_ih + b_hh (f32x2) -----------------
__global__ __launch_bounds__(256, 2) void k1_xproj(
    const float* __restrict__ X, const float* __restrict__ W,
    const float* __restrict__ bih, const float* __restrict__ bhh)
{
    __shared__ __align__(16) float As[8][132];
    __shared__ __align__(16) float Ws[8][132];
    int m0 = blockIdx.y * 128;
    int n0 = blockIdx.x * 128;
    int tid = threadIdx.x;
    int lc = tid % 8;
    int lr = tid / 8;
    int ty = tid / 16, tx = tid % 16;

    u64 acc2[8][4];
    #pragma unroll
    for (int i=0;i<8;i++)
        #pragma unroll
        for (int j=0;j<4;j++) acc2[i][j]=0ull;

    for (int k0 = 0; k0 < I_; k0 += 8) {
        #pragma unroll
        for (int p = 0; p < 4; p++) {
            int r = lr + p*32;
            As[lc][r] = X[(size_t)(m0 + r)*I_ + k0 + lc];
            Ws[lc][r] = W[(size_t)(n0 + r)*I_ + k0 + lc];
        }
        __syncthreads();
        #pragma unroll
        for (int kk = 0; kk < 8; kk++) {
            float4 a0 = *(const float4*)&As[kk][ty*4];
            float4 a1 = *(const float4*)&As[kk][64 + ty*4];
            ulonglong2 bv0 = *(const ulonglong2*)&Ws[kk][tx*4];
            ulonglong2 bv1 = *(const ulonglong2*)&Ws[kk][64 + tx*4];
            u64 bb[4] = {bv0.x, bv0.y, bv1.x, bv1.y};
            float a[8] = {a0.x,a0.y,a0.z,a0.w,a1.x,a1.y,a1.z,a1.w};
            #pragma unroll
            for (int i=0;i<8;i++) {
                u64 ad = pack2(a[i], a[i]);
                #pragma unroll
                for (int j=0;j<4;j++) acc2[i][j] = fma2(ad, bb[j], acc2[i][j]);
            }
        }
        __syncthreads();
    }
    float bias[8];
    #pragma unroll
    for (int j=0;j<8;j++) {
        int n = n0 + ((j<4)? tx*4 + j : 64 + tx*4 + (j-4));
        bias[j] = bih[n] + bhh[n];
    }
    #pragma unroll
    for (int i=0;i<8;i++) {
        int m = m0 + ((i<4)? ty*4+i : 64+ty*4+(i-4));
        float* row = g_xproj + (size_t)m*G4_ + n0;
        float c[8];
        unpack2(acc2[i][0], c[0], c[1]);
        unpack2(acc2[i][1], c[2], c[3]);
        unpack2(acc2[i][2], c[4], c[5]);
        unpack2(acc2[i][3], c[6], c[7]);
        float4 v0 = make_float4(c[0]+bias[0], c[1]+bias[1], c[2]+bias[2], c[3]+bias[3]);
        float4 v1 = make_float4(c[4]+bias[4], c[5]+bias[5], c[6]+bias[6], c[7]+bias[7]);
        *(float4*)&row[tx*4]      = v0;
        *(float4*)&row[64+tx*4]   = v1;
    }
}

// ---------------- persistent recurrence kernel --------------------------------
// 128 blocks x 256 thr. Block owns h-cols hg = bid*4..bid*4+3 (16 gate cols).
// Static smem: Wd [512][16] floats (32KB) + exch 2048 floats (8KB) = 40KB.
__global__ __launch_bounds__(256, 1) void k_rec(
    const float* __restrict__ Whh, const float* __restrict__ c0,
    float* __restrict__ out_h, float* __restrict__ out_cx)
{
    __shared__ __align__(16) float Wd[512*16];   // Wd[k*16 + q*4 + hl]
    __shared__ float exch[2048];                 // [kh][q][b][hl]

    int bid = blockIdx.x;
    int tid = threadIdx.x;

    {
        int l  = tid & 15;
        int k0 = tid >> 4;           // 0..15
        int n  = (l>>2)*H_ + bid*4 + (l&3);
        for (int k = k0; k < H_; k += 16)
            Wd[k*16 + l] = Whh[(size_t)n*H_ + k];
    }

    // pointwise cell ownership
    int pb  = tid >> 2;
    int phl = tid & 3;
    int hg  = bid*4 + phl;
    float c = c0[pb*H_ + hg];

    // GEMM warp mapping
    int w      = tid >> 5;
    int lane   = tid & 31;
    int bq     = w & 3;
    int khalf  = w >> 2;
    int bp     = lane >> 2;          // 0..7
    int q      = lane & 3;           // gate
    int b0     = bq*16 + bp*2;
    int hidx   = b0 >> 1;            // u64 index into hT row
    int kbase  = khalf * 256;

    __syncthreads();

    for (int t = 0; t < T_; ++t) {
        // ---- GEMM over this warp's k-half (packed f32x2) ----
        const u64* hp = g_hT[t & 1];
        u64 b001=0ull, b023=0ull, b101=0ull, b123=0ull;  // {hl0,hl1},{hl2,hl3} x 2 batches
        u64 hb[8];
        #pragma unroll
        for (int j=0;j<8;j++) hb[j] = ldcg64(&hp[(size_t)(kbase+j)*32 + hidx]);
        for (int kc = 0; kc < 256; kc += 8) {
            u64 hc[8];
            #pragma unroll
            for (int j=0;j<8;j++) hc[j] = hb[j];
            if (kc + 8 < 256) {
                #pragma unroll
                for (int j=0;j<8;j++)
                    hb[j] = ldcg64(&hp[(size_t)(kbase+kc+8+j)*32 + hidx]);
            }
            #pragma unroll
            for (int j=0;j<8;j++) {
                float hx, hy; unpack2(hc[j], hx, hy);
                u64 hxx = pack2(hx, hx);
                u64 hyy = pack2(hy, hy);
                ulonglong2 wv = *(const ulonglong2*)&Wd[(kbase+kc+j)*16 + q*4];
                b001 = fma2(hxx, wv.x, b001);
                b023 = fma2(hxx, wv.y, b023);
                b101 = fma2(hyy, wv.x, b101);
                b123 = fma2(hyy, wv.y, b123);
            }
        }
        // ---- exchange: exch[kh][q][b][hl] ----
        {
            int base = ((khalf*4 + q)*64 + b0)*4;
            float e0, e1;
            unpack2(b001, e0, e1); exch[base+0]=e0; exch[base+1]=e1;
            unpack2(b023, e0, e1); exch[base+2]=e0; exch[base+3]=e1;
            unpack2(b101, e0, e1); exch[base+4]=e0; exch[base+5]=e1;
            unpack2(b123, e0, e1); exch[base+6]=e0; exch[base+7]=e1;
        }
        __syncthreads();

        // ---- pointwise for cell (pb, hg); h writes go to write buffer ----
        {
            const float* xp = g_xproj + ((size_t)t*B_ + pb)*G4_;
            float ai = xp[hg]       + exch[((0*4+0)*64+pb)*4+phl] + exch[((1*4+0)*64+pb)*4+phl];
            float af = xp[H_+hg]    + exch[((0*4+1)*64+pb)*4+phl] + exch[((1*4+1)*64+pb)*4+phl];
            float ag = xp[2*H_+hg]  + exch[((0*4+2)*64+pb)*4+phl] + exch[((1*4+2)*64+pb)*4+phl];
            float ao = xp[3*H_+hg]  + exch[((0*4+3)*64+pb)*4+phl] + exch[((1*4+3)*64+pb)*4+phl];

            float ig = 1.f/(1.f+__expf(-ai));
            float fg = 1.f/(1.f+__expf(-af));
            float gg = tanhf(ag);
            float og = 1.f/(1.f+__expf(-ao));
            float cprev = c;
            float cy = fg*cprev + ig*gg;
            float hy = og*tanhf(cy);
            c = cy;

            size_t oidx = (size_t)t*BH_ + pb*H_ + hg;
            out_h[oidx] = hy;
            g_hseq[(size_t)(t+1)*BH_ + pb*H_ + hg] = hy;
            ((float*)g_hT[(t+1) & 1])[hg*B_ + pb] = hy;   // write buffer
            g_f[oidx] = fg;
            float* dp = g_d + ((size_t)t*B_ + pb)*H3_;
            dp[hg]        = gg*ig*(1.f-ig);
            dp[H_+hg]     = cprev*fg*(1.f-fg);
            dp[2*H_+hg]   = ig*(1.f-gg*gg);
            if (t == T_-1) out_cx[pb*H_ + hg] = cy;
        }

        // ---- grid barrier (release: fence+arrive; acquire: spin+sync) ----
        __threadfence();
        __syncthreads();
        if (tid == 0) {
            atomicAdd(&g_arrive, 1u);
            unsigned target = (unsigned)(NBLK_ * (t+1));
            while (ldacq32(&g_arrive) < target) { }
        }
        __syncthreads();
    }
}

// ---------------- K3: suffix forget-product scan (pipelined); ev_b ------------
__global__ void k3_suffix(float* __restrict__ out_evb)
{
    int idx = blockIdx.x*256 + threadIdx.x;   // < BH_
    int b = idx >> 9;
    int h = idx & 511;
    float p = 1.f, s0 = 0.f, s1 = 0.f, s2 = 0.f;

    // prefetch t = T-1
    float* dpp = g_d + ((size_t)(T_-1)*B_ + b)*H3_;
    float di = dpp[h], df = dpp[H_+h], dg = dpp[2*H_+h];
    float fv = g_f[(size_t)(T_-1)*BH_ + idx];

    for (int t = T_-1; t >= 0; --t) {
        float cdi = di, cdf = df, cdg = dg, cf = fv;
        float* dpc = g_d + ((size_t)t*B_ + b)*H3_;
        if (t > 0) {
            float* dpn = g_d + ((size_t)(t-1)*B_ + b)*H3_;
            di = dpn[h]; df = dpn[H_+h]; dg = dpn[2*H_+h];
            fv = g_f[(size_t)(t-1)*BH_ + idx];
        }
        float wi = cdi*p, wf = cdf*p, wg = cdg*p;
        dpc[h] = wi; dpc[H_+h] = wf; dpc[2*H_+h] = wg;
        s0 += wi; s1 += wf; s2 += wg;
        p *= cf;
    }
    out_evb[(size_t)b*H3_ + h]        = s0;
    out_evb[(size_t)b*H3_ + H_ + h]   = s1;
    out_evb[(size_t)b*H3_ + 2*H_ + h] = s2;
}

// ---------------- K4/K5: batched ev GEMM (f32x2) ------------------------------
__global__ __launch_bounds__(256, 2) void k_ev(
    const float* __restrict__ Xin, float* __restrict__ C, int Idim)
{
    __shared__ __align__(16) float As[8][132];
    __shared__ __align__(16) float Xs[8][132];
    const float* X = Xin ? Xin : (const float*)g_hseq;
    int i0 = blockIdx.x*128;
    int j0 = blockIdx.y*128;
    int b  = blockIdx.z;
    int tid = threadIdx.x;
    int ty = tid/16, tx = tid%16;
    int lk = tid >> 5;
    int lj = (tid & 31) * 4;

    u64 acc2[8][4];
    #pragma unroll
    for (int i=0;i<8;i++)
        #pragma unroll
        for (int j=0;j<4;j++) acc2[i][j]=0ull;

    for (int t0 = 0; t0 < T_; t0 += 8) {
        int t = t0 + lk;
        if (t < T_) {
            *(float4*)&As[lk][lj] = *(const float4*)&g_d[((size_t)t*B_+b)*H3_ + j0 + lj];
            *(float4*)&Xs[lk][lj] = *(const float4*)&X[((size_t)t*B_+b)*Idim + i0 + lj];
        } else {
            float4 z = make_float4(0.f,0.f,0.f,0.f);
            *(float4*)&As[lk][lj] = z;
            *(float4*)&Xs[lk][lj] = z;
        }
        __syncthreads();
        #pragma unroll
        for (int kk=0;kk<8;kk++) {
            float4 a0 = *(const float4*)&As[kk][ty*4];
            float4 a1 = *(const float4*)&As[kk][64+ty*4];
            ulonglong2 xv0 = *(const ulonglong2*)&Xs[kk][tx*4];
            ulonglong2 xv1 = *(const ulonglong2*)&Xs[kk][64+tx*4];
            u64 xx[4] = {xv0.x, xv0.y, xv1.x, xv1.y};
            float a[8] = {a0.x,a0.y,a0.z,a0.w,a1.x,a1.y,a1.z,a1.w};
            #pragma unroll
            for (int i=0;i<8;i++) {
                u64 ad = pack2(a[i], a[i]);
                #pragma unroll
                for (int j=0;j<4;j++) acc2[i][j] = fma2(ad, xx[j], acc2[i][j]);
            }
        }
        __syncthreads();
    }
    #pragma unroll
    for (int i=0;i<8;i++) {
        int j = j0 + ((i<4)? ty*4+i : 64+ty*4+(i-4));
        float* row = C + (size_t)b*H3_*Idim + (size_t)j*Idim + i0;
        float cr[8];
        unpack2(acc2[i][0], cr[0], cr[1]);
        unpack2(acc2[i][1], cr[2], cr[3]);
        unpack2(acc2[i][2], cr[4], cr[5]);
        unpack2(acc2[i][3], cr[6], cr[7]);
        *(float4*)&row[tx*4]    = make_float4(cr[0],cr[1],cr[2],cr[3]);
        *(float4*)&row[64+tx*4] = make_float4(cr[4],cr[5],cr[6],cr[7]);
    }
}

// ---------------- launch -------------------------------------------------------
extern "C" void kernel_launch(void* const* d_in, const int* in_sizes, int n_in,
                              void* d_out, int out_size)
{
    const float* input = (const float*)d_in[0];
    const float* h0    = (const float*)d_in[1];
    const float* c0    = (const float*)d_in[2];
    const float* Wih   = (const float*)d_in[3];
    const float* Whh   = (const float*)d_in[4];
    const float* bih   = (const float*)d_in[5];
    const float* bhh   = (const float*)d_in[6];

    float* out      = (float*)d_out;
    float* out_h    = out;
    float* out_cx   = out_h  + (size_t)T_*BH_;
    float* out_evih = out_cx + BH_;
    float* out_evhh = out_evih + (size_t)B_*H3_*I_;
    float* out_evb  = out_evhh + (size_t)B_*H3_*H_;

    k_init<<<128,256>>>(h0);
    k1_xproj<<<dim3(16,50),256>>>(input, Wih, bih, bhh);
    k_rec<<<NBLK_, 256>>>(Whh, c0, out_h, out_cx);
    k3_suffix<<<128,256>>>(out_evb);
    k_ev<<<dim3(I_/128, H3_/128, B_),256>>>(input, out_evih, I_);
    k_ev<<<dim3(H_/128, H3_/128, B_),256>>>(nullptr, out_evhh, H_);
}